// round 12
// baseline (speedup 1.0000x reference)
#include <cuda_runtime.h>

#define NB   64
#define SEQL 4096
#define DIM  64
#define NEG  (-10000.0f)

#define PQ 72            // pitch Qs / Ps: mult of 4 (16B aligned); 1-row stride ≡ 32B seg step;
                         // Ps bank = (8*qg+jg) mod 32 -> all 32 distinct
#define PK 68            // pitch Ks: jg rows -> 16B seg * jg, conflict-free
#define PVV 64

#define QS_OFF 0
#define KS_OFF (64*PQ)
#define VS_OFF (KS_OFF + 64*PK)
#define PS_OFF (VS_OFF + 64*PVV)
#define SMEM_FLOATS (PS_OFF + 64*PQ)
#define SMEM_BYTES  (SMEM_FLOATS * 4)

typedef unsigned long long u64;

__device__ __forceinline__ u64 ffma2(u64 a, u64 b, u64 c) {
    u64 d;
    asm("fma.rn.f32x2 %0, %1, %2, %3;" : "=l"(d) : "l"(a), "l"(b), "l"(c));
    return d;
}
__device__ __forceinline__ u64 fmul2(u64 a, u64 b) {
    u64 d;
    asm("mul.rn.f32x2 %0, %1, %2;" : "=l"(d) : "l"(a), "l"(b));
    return d;
}
__device__ __forceinline__ u64 splat2(float x) {
    u64 d; unsigned int u = __float_as_uint(x);
    asm("mov.b64 %0, {%1, %1};" : "=l"(d) : "r"(u));
    return d;
}
__device__ __forceinline__ float2 unpack2(u64 a) {
    unsigned int lo, hi;
    asm("mov.b64 {%0, %1}, %2;" : "=r"(lo), "=r"(hi) : "l"(a));
    return make_float2(__uint_as_float(lo), __uint_as_float(hi));
}

__global__ __launch_bounds__(256, 2)
void bb_attn_kernel(const float*  __restrict__ Q,
                    const float*  __restrict__ K,
                    const float*  __restrict__ V,
                    const int*    __restrict__ rand_attn,
                    const float*  __restrict__ from_mask,
                    const float*  __restrict__ to_mask,
                    const float*  __restrict__ rand_mask,
                    const float*  __restrict__ band_mask,
                    float*        __restrict__ out)
{
    extern __shared__ float sm[];
    float* Qs = sm + QS_OFF;
    float* Ks = sm + KS_OFF;
    float* Vs = sm + VS_OFF;
    float* Ps = sm + PS_OFF;

    // heavy-first remap: full-attention blocks first
    int i, bh;
    {
        int bid = blockIdx.x;
        if (bid < 64) { bh = bid >> 1; i = (bid & 1) ? (NB - 1) : 0; }
        else          { int x = bid - 64; bh = x / 62; i = 1 + (x - bh * 62); }
    }
    const int b   = bh >> 4;
    const int tid = threadIdx.x;     // 256 threads
    const int jg  = tid & 7;         // col group: cols jg + 8c
    const int qg  = tid >> 3;        // 0..31; thread owns q-rows {qg, qg+32}

    // ---- load Q (pre-scaled by 1/8, exact) ----
    const float* Qg = Q + ((size_t)bh * SEQL + (size_t)i * 64) * DIM;
    for (int f = tid; f < 1024; f += 256) {
        int row = f >> 4, c4 = (f & 15) << 2;
        float4 t4 = __ldg((const float4*)(Qg + row * DIM + c4));
        t4.x *= 0.125f; t4.y *= 0.125f; t4.z *= 0.125f; t4.w *= 0.125f;
        *(float4*)(Qs + row * PQ + c4) = t4;
    }

    // ---- key-block list ----
    const bool full = (i == 0 || i == NB - 1);
    int nt;
    int kbl[8], mtl[8], mpl[8];
    if (full) {
        nt = NB;
    } else {
        const int* ra = rand_attn + ((size_t)bh * (NB - 2) + (i - 1)) * 3;
        int r0 = __ldg(ra + 0), r1 = __ldg(ra + 1), r2 = __ldg(ra + 2);
        if (i == 1) {
            kbl[0]=0; kbl[1]=1; kbl[2]=2; kbl[3]=NB-1;
            mtl[0]=mtl[1]=mtl[2]=mtl[3]=0; mpl[0]=mpl[1]=mpl[2]=mpl[3]=0;
            kbl[4]=r0; kbl[5]=r1; kbl[6]=r2;
            mtl[4]=mtl[5]=mtl[6]=2; mpl[4]=0; mpl[5]=1; mpl[6]=2;
            nt = 7;
        } else if (i == NB - 2) {
            kbl[0]=0; kbl[1]=NB-3; kbl[2]=NB-2; kbl[3]=NB-1;
            mtl[0]=mtl[1]=mtl[2]=mtl[3]=0; mpl[0]=mpl[1]=mpl[2]=mpl[3]=0;
            kbl[4]=r0; kbl[5]=r1; kbl[6]=r2;
            mtl[4]=mtl[5]=mtl[6]=2; mpl[4]=0; mpl[5]=1; mpl[6]=2;
            nt = 7;
        } else {
            kbl[0]=0;    mtl[0]=0; mpl[0]=0;
            kbl[1]=i-1;  mtl[1]=1; mpl[1]=0;
            kbl[2]=i;    mtl[2]=1; mpl[2]=1;
            kbl[3]=i+1;  mtl[3]=1; mpl[3]=2;
            kbl[4]=r0;   mtl[4]=2; mpl[4]=0;
            kbl[5]=r1;   mtl[5]=2; mpl[5]=1;
            kbl[6]=r2;   mtl[6]=2; mpl[6]=2;
            kbl[7]=NB-1; mtl[7]=0; mpl[7]=0;
            nt = 8;
        }
    }

    // ---- packed accumulators: 2 rows x dims [4jg,+4)∪[32+4jg,+4) ----
    u64 acc2[2][4];
    float mrow[2], lrow[2];
    #pragma unroll
    for (int r = 0; r < 2; r++) {
        mrow[r] = -1e30f; lrow[r] = 0.0f;
        #pragma unroll
        for (int p = 0; p < 4; p++) acc2[r][p] = 0ull;
    }

    for (int t = 0; t < nt; t++) {
        int kb, mt, mp;
        if (full) { kb = t; mt = 0; mp = 0; }
        else      { kb = kbl[t]; mt = mtl[t]; mp = mpl[t]; }

        __syncthreads();

        // ---- load K, V tile ----
        const float* Kg = K + ((size_t)bh * SEQL + (size_t)kb * 64) * DIM;
        const float* Vg = V + ((size_t)bh * SEQL + (size_t)kb * 64) * DIM;
        for (int f = tid; f < 1024; f += 256) {
            int row = f >> 4, c4 = (f & 15) << 2;
            float4 kk = __ldg((const float4*)(Kg + row * DIM + c4));
            *(float4*)(Ks + row * PK + c4) = kk;
            float4 vv = __ldg((const float4*)(Vg + row * DIM + c4));
            *(float4*)(Vs + row * PVV + c4) = vv;
        }
        __syncthreads();

        // ---- QK^T with f32x2: 2 rows x 8 cols, full-width accumulators ----
        u64 s2[2][8];
        #pragma unroll
        for (int r = 0; r < 2; r++)
            #pragma unroll
            for (int c = 0; c < 8; c++) s2[r][c] = 0ull;

        #pragma unroll 2
        for (int d4 = 0; d4 < 16; d4++) {
            ulonglong2 qv[2], kv[8];
            qv[0] = *(const ulonglong2*)(const void*)(Qs + qg * PQ + (d4 << 2));
            qv[1] = *(const ulonglong2*)(const void*)(Qs + (qg + 32) * PQ + (d4 << 2));
            #pragma unroll
            for (int c = 0; c < 8; c++)
                kv[c] = *(const ulonglong2*)(const void*)(Ks + (jg + (c << 3)) * PK + (d4 << 2));
            #pragma unroll
            for (int r = 0; r < 2; r++)
                #pragma unroll
                for (int c = 0; c < 8; c++) {
                    s2[r][c] = ffma2(qv[r].x, kv[c].x, s2[r][c]);
                    s2[r][c] = ffma2(qv[r].y, kv[c].y, s2[r][c]);
                }
        }

        // reduce packed pairs -> scalar scores
        float s[2][8];
        #pragma unroll
        for (int r = 0; r < 2; r++)
            #pragma unroll
            for (int c = 0; c < 8; c++) {
                float2 u = unpack2(s2[r][c]);
                s[r][c] = u.x + u.y;
            }

        // ---- mask (q-row for slot r is qg + 32r) ----
        if (mt == 0) {
            const float* tmp = to_mask + (size_t)b * SEQL + (size_t)kb * 64 + jg;
            float tadd[8];
            #pragma unroll
            for (int c = 0; c < 8; c++)
                tadd[c] = (1.0f - __ldg(tmp + (c << 3))) * NEG;
            #pragma unroll
            for (int r = 0; r < 2; r++)
                #pragma unroll
                for (int c = 0; c < 8; c++)
                    s[r][c] += tadd[c];
        } else if (mt == 1) {
            const float* bm = band_mask
                + (((size_t)b * (NB - 4) + (i - 2)) * 64) * 192 + mp * 64 + jg;
            #pragma unroll
            for (int r = 0; r < 2; r++) {
                const float* bmr = bm + (size_t)(qg + (r << 5)) * 192;
                #pragma unroll
                for (int c = 0; c < 8; c++)
                    s[r][c] += (1.0f - __ldg(bmr + (c << 3))) * NEG;
            }
        } else {
            const float* rm = rand_mask
                + (((size_t)bh * (NB - 2) + (i - 1)) * 64) * 192 + mp * 64 + jg;
            #pragma unroll
            for (int r = 0; r < 2; r++) {
                const float* rmr = rm + (size_t)(qg + (r << 5)) * 192;
                #pragma unroll
                for (int c = 0; c < 8; c++)
                    s[r][c] += (1.0f - __ldg(rmr + (c << 3))) * NEG;
            }
        }

        // ---- online softmax (8-lane row groups) ----
        #pragma unroll
        for (int r = 0; r < 2; r++) {
            float mx = s[r][0];
            #pragma unroll
            for (int c = 1; c < 8; c++) mx = fmaxf(mx, s[r][c]);
            mx = fmaxf(mx, __shfl_xor_sync(0xffffffffu, mx, 1));
            mx = fmaxf(mx, __shfl_xor_sync(0xffffffffu, mx, 2));
            mx = fmaxf(mx, __shfl_xor_sync(0xffffffffu, mx, 4));
            float mnew = fmaxf(mrow[r], mx);
            float corr = __expf(mrow[r] - mnew);
            float ls = 0.0f;
            #pragma unroll
            for (int c = 0; c < 8; c++) {
                float p = __expf(s[r][c] - mnew);
                s[r][c] = p;
                ls += p;
            }
            ls += __shfl_xor_sync(0xffffffffu, ls, 1);
            ls += __shfl_xor_sync(0xffffffffu, ls, 2);
            ls += __shfl_xor_sync(0xffffffffu, ls, 4);
            lrow[r] = lrow[r] * corr + ls;
            mrow[r] = mnew;
            u64 corr2 = splat2(corr);
            #pragma unroll
            for (int p = 0; p < 4; p++) acc2[r][p] = fmul2(acc2[r][p], corr2);
            #pragma unroll
            for (int c = 0; c < 8; c++)
                Ps[(qg + (r << 5)) * PQ + jg + (c << 3)] = s[r][c];
        }
        __syncthreads();

        // ---- PV with f32x2, paired over output dims ----
        #pragma unroll 2
        for (int j4 = 0; j4 < 16; j4++) {
            float4 pv[2];
            pv[0] = *(const float4*)(Ps + qg * PQ + (j4 << 2));
            pv[1] = *(const float4*)(Ps + (qg + 32) * PQ + (j4 << 2));
            ulonglong2 va[4], vb[4];
            #pragma unroll
            for (int jj = 0; jj < 4; jj++) {
                const float* vrow = Vs + ((j4 << 2) + jj) * PVV;
                va[jj] = *(const ulonglong2*)(const void*)(vrow + (jg << 2));
                vb[jj] = *(const ulonglong2*)(const void*)(vrow + 32 + (jg << 2));
            }
            #pragma unroll
            for (int r = 0; r < 2; r++) {
                float pr[4] = { pv[r].x, pv[r].y, pv[r].z, pv[r].w };
                #pragma unroll
                for (int jj = 0; jj < 4; jj++) {
                    u64 p2 = splat2(pr[jj]);
                    acc2[r][0] = ffma2(p2, va[jj].x, acc2[r][0]);
                    acc2[r][1] = ffma2(p2, va[jj].y, acc2[r][1]);
                    acc2[r][2] = ffma2(p2, vb[jj].x, acc2[r][2]);
                    acc2[r][3] = ffma2(p2, vb[jj].y, acc2[r][3]);
                }
            }
        }
    }

    // ---- epilogue (q-row for slot r is qg + 32r) ----
    float* og = out + ((size_t)bh * SEQL + (size_t)i * 64) * DIM;
    #pragma unroll
    for (int r = 0; r < 2; r++) {
        int qrow = qg + (r << 5);
        float fm = __ldg(from_mask + (size_t)b * SEQL + (size_t)i * 64 + qrow);
        float inv = fm / lrow[r];
        float2 a0 = unpack2(acc2[r][0]);
        float2 a1 = unpack2(acc2[r][1]);
        float2 b0 = unpack2(acc2[r][2]);
        float2 b1 = unpack2(acc2[r][3]);
        float4 oa = make_float4(a0.x*inv, a0.y*inv, a1.x*inv, a1.y*inv);
        float4 ob = make_float4(b0.x*inv, b0.y*inv, b1.x*inv, b1.y*inv);
        *(float4*)(og + qrow * DIM + (jg << 2))      = oa;
        *(float4*)(og + qrow * DIM + 32 + (jg << 2)) = ob;
    }
}

extern "C" void kernel_launch(void* const* d_in, const int* in_sizes, int n_in,
                              void* d_out, int out_size)
{
    const float* Q  = (const float*)d_in[0];
    const float* K  = (const float*)d_in[1];
    const float* V  = (const float*)d_in[2];
    const int*   RA = (const int*)  d_in[3];
    const float* FM = (const float*)d_in[4];
    const float* TM = (const float*)d_in[5];
    const float* RM = (const float*)d_in[6];
    const float* BM = (const float*)d_in[7];
    float* O = (float*)d_out;

    cudaFuncSetAttribute(bb_attn_kernel,
                         cudaFuncAttributeMaxDynamicSharedMemorySize, SMEM_BYTES);

    dim3 grid(2 * 16 * NB);
    bb_attn_kernel<<<grid, 256, SMEM_BYTES>>>(Q, K, V, RA, FM, TM, RM, BM, O);
}

// round 13
// speedup vs baseline: 1.0021x; 1.0021x over previous
#include <cuda_runtime.h>

#define NB   64
#define SEQL 4096
#define DIM  64
#define NEG  (-10000.0f)

#define PQ 72            // pitch Qs / Ps: mult of 4 (16B aligned); 1-row stride ≡ 32B seg step;
                         // Ps bank = (8*qg+jg) mod 32 -> all 32 distinct
#define PK 68            // pitch Ks: jg rows -> 16B seg * jg, conflict-free
#define PVV 64

#define QS_OFF 0
#define KS_OFF (64*PQ)
#define VS_OFF (KS_OFF + 64*PK)
#define PS_OFF (VS_OFF + 64*PVV)
#define SMEM_FLOATS (PS_OFF + 64*PQ)
#define SMEM_BYTES  (SMEM_FLOATS * 4)

typedef unsigned long long u64;

__device__ __forceinline__ u64 ffma2(u64 a, u64 b, u64 c) {
    u64 d;
    asm("fma.rn.f32x2 %0, %1, %2, %3;" : "=l"(d) : "l"(a), "l"(b), "l"(c));
    return d;
}
__device__ __forceinline__ u64 fmul2(u64 a, u64 b) {
    u64 d;
    asm("mul.rn.f32x2 %0, %1, %2;" : "=l"(d) : "l"(a), "l"(b));
    return d;
}
__device__ __forceinline__ u64 splat2(float x) {
    u64 d; unsigned int u = __float_as_uint(x);
    asm("mov.b64 %0, {%1, %1};" : "=l"(d) : "r"(u));
    return d;
}
__device__ __forceinline__ float2 unpack2(u64 a) {
    unsigned int lo, hi;
    asm("mov.b64 {%0, %1}, %2;" : "=r"(lo), "=r"(hi) : "l"(a));
    return make_float2(__uint_as_float(lo), __uint_as_float(hi));
}

__global__ __launch_bounds__(256, 2)
void bb_attn_kernel(const float*  __restrict__ Q,
                    const float*  __restrict__ K,
                    const float*  __restrict__ V,
                    const int*    __restrict__ rand_attn,
                    const float*  __restrict__ from_mask,
                    const float*  __restrict__ to_mask,
                    const float*  __restrict__ rand_mask,
                    const float*  __restrict__ band_mask,
                    float*        __restrict__ out)
{
    extern __shared__ float sm[];
    float* Qs = sm + QS_OFF;
    float* Ks = sm + KS_OFF;
    float* Vs = sm + VS_OFF;
    float* Ps = sm + PS_OFF;

    // heavy-first remap: full-attention blocks first
    int i, bh;
    {
        int bid = blockIdx.x;
        if (bid < 64) { bh = bid >> 1; i = (bid & 1) ? (NB - 1) : 0; }
        else          { int x = bid - 64; bh = x / 62; i = 1 + (x - bh * 62); }
    }
    const int b   = bh >> 4;
    const int tid = threadIdx.x;     // 256 threads
    const int jg  = tid & 7;         // col group: cols jg + 8c
    const int qg  = tid >> 3;        // 0..31; thread owns q-rows {qg, qg+32}

    // ---- load Q (pre-scaled by 1/8, exact) ----
    const float* Qg = Q + ((size_t)bh * SEQL + (size_t)i * 64) * DIM;
    for (int f = tid; f < 1024; f += 256) {
        int row = f >> 4, c4 = (f & 15) << 2;
        float4 t4 = __ldg((const float4*)(Qg + row * DIM + c4));
        t4.x *= 0.125f; t4.y *= 0.125f; t4.z *= 0.125f; t4.w *= 0.125f;
        *(float4*)(Qs + row * PQ + c4) = t4;
    }

    // ---- key-block list ----
    const bool full = (i == 0 || i == NB - 1);
    int nt;
    int kbl[8], mtl[8], mpl[8];
    if (full) {
        nt = NB;
    } else {
        const int* ra = rand_attn + ((size_t)bh * (NB - 2) + (i - 1)) * 3;
        int r0 = __ldg(ra + 0), r1 = __ldg(ra + 1), r2 = __ldg(ra + 2);
        if (i == 1) {
            kbl[0]=0; kbl[1]=1; kbl[2]=2; kbl[3]=NB-1;
            mtl[0]=mtl[1]=mtl[2]=mtl[3]=0; mpl[0]=mpl[1]=mpl[2]=mpl[3]=0;
            kbl[4]=r0; kbl[5]=r1; kbl[6]=r2;
            mtl[4]=mtl[5]=mtl[6]=2; mpl[4]=0; mpl[5]=1; mpl[6]=2;
            nt = 7;
        } else if (i == NB - 2) {
            kbl[0]=0; kbl[1]=NB-3; kbl[2]=NB-2; kbl[3]=NB-1;
            mtl[0]=mtl[1]=mtl[2]=mtl[3]=0; mpl[0]=mpl[1]=mpl[2]=mpl[3]=0;
            kbl[4]=r0; kbl[5]=r1; kbl[6]=r2;
            mtl[4]=mtl[5]=mtl[6]=2; mpl[4]=0; mpl[5]=1; mpl[6]=2;
            nt = 7;
        } else {
            kbl[0]=0;    mtl[0]=0; mpl[0]=0;
            kbl[1]=i-1;  mtl[1]=1; mpl[1]=0;
            kbl[2]=i;    mtl[2]=1; mpl[2]=1;
            kbl[3]=i+1;  mtl[3]=1; mpl[3]=2;
            kbl[4]=r0;   mtl[4]=2; mpl[4]=0;
            kbl[5]=r1;   mtl[5]=2; mpl[5]=1;
            kbl[6]=r2;   mtl[6]=2; mpl[6]=2;
            kbl[7]=NB-1; mtl[7]=0; mpl[7]=0;
            nt = 8;
        }
    }

    // ---- packed accumulators: 2 rows x dims [4jg,+4)∪[32+4jg,+4) ----
    u64 acc2[2][4];
    float mrow[2], lrow[2];
    #pragma unroll
    for (int r = 0; r < 2; r++) {
        mrow[r] = -1e30f; lrow[r] = 0.0f;
        #pragma unroll
        for (int p = 0; p < 4; p++) acc2[r][p] = 0ull;
    }

    for (int t = 0; t < nt; t++) {
        int kb, mt, mp;
        if (full) { kb = t; mt = 0; mp = 0; }
        else      { kb = kbl[t]; mt = mtl[t]; mp = mpl[t]; }

        __syncthreads();

        // ---- load K, V tile ----
        const float* Kg = K + ((size_t)bh * SEQL + (size_t)kb * 64) * DIM;
        const float* Vg = V + ((size_t)bh * SEQL + (size_t)kb * 64) * DIM;
        for (int f = tid; f < 1024; f += 256) {
            int row = f >> 4, c4 = (f & 15) << 2;
            float4 kk = __ldg((const float4*)(Kg + row * DIM + c4));
            *(float4*)(Ks + row * PK + c4) = kk;
            float4 vv = __ldg((const float4*)(Vg + row * DIM + c4));
            *(float4*)(Vs + row * PVV + c4) = vv;
        }
        __syncthreads();

        // ---- QK^T with f32x2: 2 rows x 8 cols, full-width accumulators ----
        u64 s2[2][8];
        #pragma unroll
        for (int r = 0; r < 2; r++)
            #pragma unroll
            for (int c = 0; c < 8; c++) s2[r][c] = 0ull;

        #pragma unroll 2
        for (int d4 = 0; d4 < 16; d4++) {
            ulonglong2 qv[2], kv[8];
            qv[0] = *(const ulonglong2*)(const void*)(Qs + qg * PQ + (d4 << 2));
            qv[1] = *(const ulonglong2*)(const void*)(Qs + (qg + 32) * PQ + (d4 << 2));
            #pragma unroll
            for (int c = 0; c < 8; c++)
                kv[c] = *(const ulonglong2*)(const void*)(Ks + (jg + (c << 3)) * PK + (d4 << 2));
            #pragma unroll
            for (int r = 0; r < 2; r++)
                #pragma unroll
                for (int c = 0; c < 8; c++) {
                    s2[r][c] = ffma2(qv[r].x, kv[c].x, s2[r][c]);
                    s2[r][c] = ffma2(qv[r].y, kv[c].y, s2[r][c]);
                }
        }

        // reduce packed pairs -> scalar scores
        float s[2][8];
        #pragma unroll
        for (int r = 0; r < 2; r++)
            #pragma unroll
            for (int c = 0; c < 8; c++) {
                float2 u = unpack2(s2[r][c]);
                s[r][c] = u.x + u.y;
            }

        // ---- mask (q-row for slot r is qg + 32r) ----
        if (mt == 0) {
            const float* tmp = to_mask + (size_t)b * SEQL + (size_t)kb * 64 + jg;
            float tadd[8];
            #pragma unroll
            for (int c = 0; c < 8; c++)
                tadd[c] = (1.0f - __ldg(tmp + (c << 3))) * NEG;
            #pragma unroll
            for (int r = 0; r < 2; r++)
                #pragma unroll
                for (int c = 0; c < 8; c++)
                    s[r][c] += tadd[c];
        } else if (mt == 1) {
            const float* bm = band_mask
                + (((size_t)b * (NB - 4) + (i - 2)) * 64) * 192 + mp * 64 + jg;
            #pragma unroll
            for (int r = 0; r < 2; r++) {
                const float* bmr = bm + (size_t)(qg + (r << 5)) * 192;
                #pragma unroll
                for (int c = 0; c < 8; c++)
                    s[r][c] += (1.0f - __ldg(bmr + (c << 3))) * NEG;
            }
        } else {
            const float* rm = rand_mask
                + (((size_t)bh * (NB - 2) + (i - 1)) * 64) * 192 + mp * 64 + jg;
            #pragma unroll
            for (int r = 0; r < 2; r++) {
                const float* rmr = rm + (size_t)(qg + (r << 5)) * 192;
                #pragma unroll
                for (int c = 0; c < 8; c++)
                    s[r][c] += (1.0f - __ldg(rmr + (c << 3))) * NEG;
            }
        }

        // ---- online softmax (8-lane row groups) ----
        #pragma unroll
        for (int r = 0; r < 2; r++) {
            float mx = s[r][0];
            #pragma unroll
            for (int c = 1; c < 8; c++) mx = fmaxf(mx, s[r][c]);
            mx = fmaxf(mx, __shfl_xor_sync(0xffffffffu, mx, 1));
            mx = fmaxf(mx, __shfl_xor_sync(0xffffffffu, mx, 2));
            mx = fmaxf(mx, __shfl_xor_sync(0xffffffffu, mx, 4));
            float mnew = fmaxf(mrow[r], mx);
            float corr = __expf(mrow[r] - mnew);
            float ls = 0.0f;
            #pragma unroll
            for (int c = 0; c < 8; c++) {
                float p = __expf(s[r][c] - mnew);
                s[r][c] = p;
                ls += p;
            }
            ls += __shfl_xor_sync(0xffffffffu, ls, 1);
            ls += __shfl_xor_sync(0xffffffffu, ls, 2);
            ls += __shfl_xor_sync(0xffffffffu, ls, 4);
            lrow[r] = lrow[r] * corr + ls;
            mrow[r] = mnew;
            u64 corr2 = splat2(corr);
            #pragma unroll
            for (int p = 0; p < 4; p++) acc2[r][p] = fmul2(acc2[r][p], corr2);
            #pragma unroll
            for (int c = 0; c < 8; c++)
                Ps[(qg + (r << 5)) * PQ + jg + (c << 3)] = s[r][c];
        }
        __syncthreads();

        // ---- PV with f32x2, paired over output dims ----
        #pragma unroll 2
        for (int j4 = 0; j4 < 16; j4++) {
            float4 pv[2];
            pv[0] = *(const float4*)(Ps + qg * PQ + (j4 << 2));
            pv[1] = *(const float4*)(Ps + (qg + 32) * PQ + (j4 << 2));
            ulonglong2 va[4], vb[4];
            #pragma unroll
            for (int jj = 0; jj < 4; jj++) {
                const float* vrow = Vs + ((j4 << 2) + jj) * PVV;
                va[jj] = *(const ulonglong2*)(const void*)(vrow + (jg << 2));
                vb[jj] = *(const ulonglong2*)(const void*)(vrow + 32 + (jg << 2));
            }
            #pragma unroll
            for (int r = 0; r < 2; r++) {
                float pr[4] = { pv[r].x, pv[r].y, pv[r].z, pv[r].w };
                #pragma unroll
                for (int jj = 0; jj < 4; jj++) {
                    u64 p2 = splat2(pr[jj]);
                    acc2[r][0] = ffma2(p2, va[jj].x, acc2[r][0]);
                    acc2[r][1] = ffma2(p2, va[jj].y, acc2[r][1]);
                    acc2[r][2] = ffma2(p2, vb[jj].x, acc2[r][2]);
                    acc2[r][3] = ffma2(p2, vb[jj].y, acc2[r][3]);
                }
            }
        }
    }

    // ---- epilogue (q-row for slot r is qg + 32r) ----
    float* og = out + ((size_t)bh * SEQL + (size_t)i * 64) * DIM;
    #pragma unroll
    for (int r = 0; r < 2; r++) {
        int qrow = qg + (r << 5);
        float fm = __ldg(from_mask + (size_t)b * SEQL + (size_t)i * 64 + qrow);
        float inv = fm / lrow[r];
        float2 a0 = unpack2(acc2[r][0]);
        float2 a1 = unpack2(acc2[r][1]);
        float2 b0 = unpack2(acc2[r][2]);
        float2 b1 = unpack2(acc2[r][3]);
        float4 oa = make_float4(a0.x*inv, a0.y*inv, a1.x*inv, a1.y*inv);
        float4 ob = make_float4(b0.x*inv, b0.y*inv, b1.x*inv, b1.y*inv);
        *(float4*)(og + qrow * DIM + (jg << 2))      = oa;
        *(float4*)(og + qrow * DIM + 32 + (jg << 2)) = ob;
    }
}

extern "C" void kernel_launch(void* const* d_in, const int* in_sizes, int n_in,
                              void* d_out, int out_size)
{
    const float* Q  = (const float*)d_in[0];
    const float* K  = (const float*)d_in[1];
    const float* V  = (const float*)d_in[2];
    const int*   RA = (const int*)  d_in[3];
    const float* FM = (const float*)d_in[4];
    const float* TM = (const float*)d_in[5];
    const float* RM = (const float*)d_in[6];
    const float* BM = (const float*)d_in[7];
    float* O = (float*)d_out;

    cudaFuncSetAttribute(bb_attn_kernel,
                         cudaFuncAttributeMaxDynamicSharedMemorySize, SMEM_BYTES);

    dim3 grid(2 * 16 * NB);
    bb_attn_kernel<<<grid, 256, SMEM_BYTES>>>(Q, K, V, RA, FM, TM, RM, BM, O);
}

// round 15
// speedup vs baseline: 1.8584x; 1.8545x over previous
#include <cuda_runtime.h>
#include <cuda_bf16.h>
#include <cstdint>

#define NB    64
#define SEQL  4096
#define NEGM  (-10000.0f)

#define PITCH 144                 // 72 bf16 per row: conflict-free fragment LDS
#define O_QH  0
#define O_QL  (O_QH + 64*PITCH)
#define O_KH  (O_QL + 64*PITCH)
#define O_KL  (O_KH + 64*PITCH)
#define O_VH  (O_KL + 64*PITCH)   // V transposed: [dim][key]
#define O_VL  (O_VH + 64*PITCH)
#define SMEM_TOTAL (O_VL + 64*PITCH)   // 55296 B

static __device__ __forceinline__ void mma_bf16(float* d, const uint32_t* a,
                                                uint32_t b0, uint32_t b1) {
    asm volatile("mma.sync.aligned.m16n8k16.row.col.f32.bf16.bf16.f32 "
                 "{%0,%1,%2,%3}, {%4,%5,%6,%7}, {%8,%9}, {%0,%1,%2,%3};"
                 : "+f"(d[0]), "+f"(d[1]), "+f"(d[2]), "+f"(d[3])
                 : "r"(a[0]), "r"(a[1]), "r"(a[2]), "r"(a[3]), "r"(b0), "r"(b1));
}
// split (x,y) into packed bf16 hi word + residual-lo word (low half = x)
static __device__ __forceinline__ void split2(float x, float y, uint32_t& h, uint32_t& l) {
    __nv_bfloat162 bh = __floats2bfloat162_rn(x, y);
    float rx = __bfloat162float(__low2bfloat16(bh));
    float ry = __bfloat162float(__high2bfloat16(bh));
    __nv_bfloat162 bl = __floats2bfloat162_rn(x - rx, y - ry);
    h = *(uint32_t*)&bh; l = *(uint32_t*)&bl;
}

__global__ __launch_bounds__(128)
void bb_hmma_kernel(const float*  __restrict__ Q,
                    const float*  __restrict__ K,
                    const float*  __restrict__ V,
                    const int*    __restrict__ rand_attn,
                    const float*  __restrict__ from_mask,
                    const float*  __restrict__ to_mask,
                    const float*  __restrict__ rand_mask,
                    const float*  __restrict__ band_mask,
                    float*        __restrict__ out)
{
    extern __shared__ char smc[];

    // heavy-first remap: full-attention blocks first
    int i, bh;
    {
        int bid = blockIdx.x;
        if (bid < 64) { bh = bid >> 1; i = (bid & 1) ? (NB - 1) : 0; }
        else          { int x = bid - 64; bh = x / 62; i = 1 + (x - bh * 62); }
    }
    const int b    = bh >> 4;
    const int tid  = threadIdx.x;
    const int wid  = tid >> 5;
    const int lane = tid & 31;
    const int qd   = lane >> 2;          // 0..7
    const int qq   = lane & 3;           // 0..3
    const int r_lo = wid * 16 + qd;      // q-rows owned: r_lo, r_lo+8
    const int r_hi = r_lo + 8;

    // ---- load Q block -> bf16 hi/lo smem (pre-scaled by 1/8, exact) ----
    {
        const float* Qg = Q + ((size_t)bh * SEQL + (size_t)i * 64) * 64;
        for (int f = tid; f < 1024; f += 128) {
            int row = f >> 4, c4 = (f & 15) << 2;
            float4 t = __ldg((const float4*)(Qg + row * 64 + c4));
            t.x *= 0.125f; t.y *= 0.125f; t.z *= 0.125f; t.w *= 0.125f;
            uint32_t h0, l0, h1, l1;
            split2(t.x, t.y, h0, l0);
            split2(t.z, t.w, h1, l1);
            char* base = smc + row * PITCH + c4 * 2;
            *(uint32_t*)(base + O_QH)     = h0;
            *(uint32_t*)(base + O_QH + 4) = h1;
            *(uint32_t*)(base + O_QL)     = l0;
            *(uint32_t*)(base + O_QL + 4) = l1;
        }
    }

    // ---- key-block list (same logic as reference) ----
    const bool full = (i == 0 || i == NB - 1);
    int nt;
    int kbl[8], mtl[8], mpl[8];
    if (full) {
        nt = NB;
    } else {
        const int* ra = rand_attn + ((size_t)bh * (NB - 2) + (i - 1)) * 3;
        int r0 = __ldg(ra), r1 = __ldg(ra + 1), r2 = __ldg(ra + 2);
        if (i == 1) {
            kbl[0]=0; kbl[1]=1; kbl[2]=2; kbl[3]=NB-1;
            mtl[0]=mtl[1]=mtl[2]=mtl[3]=0; mpl[0]=mpl[1]=mpl[2]=mpl[3]=0;
            kbl[4]=r0; kbl[5]=r1; kbl[6]=r2;
            mtl[4]=mtl[5]=mtl[6]=2; mpl[4]=0; mpl[5]=1; mpl[6]=2;
            nt = 7;
        } else if (i == NB - 2) {
            kbl[0]=0; kbl[1]=NB-3; kbl[2]=NB-2; kbl[3]=NB-1;
            mtl[0]=mtl[1]=mtl[2]=mtl[3]=0; mpl[0]=mpl[1]=mpl[2]=mpl[3]=0;
            kbl[4]=r0; kbl[5]=r1; kbl[6]=r2;
            mtl[4]=mtl[5]=mtl[6]=2; mpl[4]=0; mpl[5]=1; mpl[6]=2;
            nt = 7;
        } else {
            kbl[0]=0;    mtl[0]=0; mpl[0]=0;
            kbl[1]=i-1;  mtl[1]=1; mpl[1]=0;
            kbl[2]=i;    mtl[2]=1; mpl[2]=1;
            kbl[3]=i+1;  mtl[3]=1; mpl[3]=2;
            kbl[4]=r0;   mtl[4]=2; mpl[4]=0;
            kbl[5]=r1;   mtl[5]=2; mpl[5]=1;
            kbl[6]=r2;   mtl[6]=2; mpl[6]=2;
            kbl[7]=NB-1; mtl[7]=0; mpl[7]=0;
            nt = 8;
        }
    }

    // persistent O accumulators (8 n-tiles x 4 regs) and row sums
    float o[8][4];
    #pragma unroll
    for (int c = 0; c < 8; c++)
        #pragma unroll
        for (int u = 0; u < 4; u++) o[c][u] = 0.0f;
    float lsum0 = 0.0f, lsum1 = 0.0f;

    for (int t = 0; t < nt; t++) {
        int kb, mt, mp;
        if (full) { kb = t; mt = 0; mp = 0; }
        else      { kb = kbl[t]; mt = mtl[t]; mp = mpl[t]; }

        __syncthreads();   // previous tile's MMAs done reading K/V smem

        // ---- load K (row-major) and V (transposed) -> bf16 hi/lo smem ----
        {
            const float* Kg = K + ((size_t)bh * SEQL + (size_t)kb * 64) * 64;
            const float* Vg = V + ((size_t)bh * SEQL + (size_t)kb * 64) * 64;
            for (int f = tid; f < 1024; f += 128) {
                int row = f >> 4, c4 = (f & 15) << 2;
                float4 kk = __ldg((const float4*)(Kg + row * 64 + c4));
                uint32_t h0, l0, h1, l1;
                split2(kk.x, kk.y, h0, l0);
                split2(kk.z, kk.w, h1, l1);
                char* kb_ = smc + row * PITCH + c4 * 2;
                *(uint32_t*)(kb_ + O_KH)     = h0;
                *(uint32_t*)(kb_ + O_KH + 4) = h1;
                *(uint32_t*)(kb_ + O_KL)     = l0;
                *(uint32_t*)(kb_ + O_KL + 4) = l1;
                float4 vv = __ldg((const float4*)(Vg + row * 64 + c4));
                float vx[4] = { vv.x, vv.y, vv.z, vv.w };
                #pragma unroll
                for (int jj = 0; jj < 4; jj++) {
                    __nv_bfloat16 hbf = __float2bfloat16(vx[jj]);
                    float rh = __bfloat162float(hbf);
                    __nv_bfloat16 lbf = __float2bfloat16(vx[jj] - rh);
                    char* vb_ = smc + (c4 + jj) * PITCH + row * 2;
                    *(uint16_t*)(vb_ + O_VH) = *(uint16_t*)&hbf;
                    *(uint16_t*)(vb_ + O_VL) = *(uint16_t*)&lbf;
                }
            }
        }
        __syncthreads();

        // ---- QK^T on HMMA: S[8 tiles][4 regs] ----
        float s[8][4];
        #pragma unroll
        for (int c = 0; c < 8; c++)
            #pragma unroll
            for (int u = 0; u < 4; u++) s[c][u] = 0.0f;

        #pragma unroll
        for (int kt = 0; kt < 4; kt++) {
            uint32_t aH[4], aL[4];
            {
                const char* qlo = smc + r_lo * PITCH + kt * 32 + qq * 4;
                const char* qhi = smc + r_hi * PITCH + kt * 32 + qq * 4;
                aH[0] = *(const uint32_t*)(qlo + O_QH);
                aH[1] = *(const uint32_t*)(qhi + O_QH);
                aH[2] = *(const uint32_t*)(qlo + O_QH + 16);
                aH[3] = *(const uint32_t*)(qhi + O_QH + 16);
                aL[0] = *(const uint32_t*)(qlo + O_QL);
                aL[1] = *(const uint32_t*)(qhi + O_QL);
                aL[2] = *(const uint32_t*)(qlo + O_QL + 16);
                aL[3] = *(const uint32_t*)(qhi + O_QL + 16);
            }
            #pragma unroll
            for (int c = 0; c < 8; c++) {
                const char* kp = smc + (c * 8 + qd) * PITCH + kt * 32 + qq * 4;
                uint32_t bH0 = *(const uint32_t*)(kp + O_KH);
                uint32_t bH1 = *(const uint32_t*)(kp + O_KH + 16);
                uint32_t bL0 = *(const uint32_t*)(kp + O_KL);
                uint32_t bL1 = *(const uint32_t*)(kp + O_KL + 16);
                mma_bf16(s[c], aH, bH0, bH1);
                mma_bf16(s[c], aH, bL0, bL1);
                mma_bf16(s[c], aL, bH0, bH1);
            }
        }

        // ---- mask + exp (registers; cols for tile c: 8c+2qq, +1) ----
        if (mt == 0) {
            const float* tmp = to_mask + (size_t)b * SEQL + (size_t)kb * 64;
            #pragma unroll
            for (int c = 0; c < 8; c++) {
                float2 m = __ldg((const float2*)(tmp + c * 8 + qq * 2));
                float t0 = (1.0f - m.x) * NEGM, t1 = (1.0f - m.y) * NEGM;
                s[c][0] += t0; s[c][1] += t1; s[c][2] += t0; s[c][3] += t1;
            }
        } else {
            const float* mbase = (mt == 1)
                ? band_mask + (((size_t)b  * (NB - 4) + (i - 2)) * 64) * 192 + mp * 64
                : rand_mask + (((size_t)bh * (NB - 2) + (i - 1)) * 64) * 192 + mp * 64;
            const float* mlo = mbase + (size_t)r_lo * 192;
            const float* mhi = mbase + (size_t)r_hi * 192;
            #pragma unroll
            for (int c = 0; c < 8; c++) {
                float2 m0 = __ldg((const float2*)(mlo + c * 8 + qq * 2));
                float2 m1 = __ldg((const float2*)(mhi + c * 8 + qq * 2));
                s[c][0] += (1.0f - m0.x) * NEGM; s[c][1] += (1.0f - m0.y) * NEGM;
                s[c][2] += (1.0f - m1.x) * NEGM; s[c][3] += (1.0f - m1.y) * NEGM;
            }
        }
        #pragma unroll
        for (int c = 0; c < 8; c++) {
            s[c][0] = __expf(s[c][0]); s[c][1] = __expf(s[c][1]);
            s[c][2] = __expf(s[c][2]); s[c][3] = __expf(s[c][3]);
            lsum0 += s[c][0] + s[c][1];
            lsum1 += s[c][2] + s[c][3];
        }

        // ---- PV on HMMA: P A-frags are direct repacks of S regs ----
        #pragma unroll
        for (int kt = 0; kt < 4; kt++) {
            uint32_t aH[4], aL[4];
            split2(s[2*kt][0],   s[2*kt][1],   aH[0], aL[0]);
            split2(s[2*kt][2],   s[2*kt][3],   aH[1], aL[1]);
            split2(s[2*kt+1][0], s[2*kt+1][1], aH[2], aL[2]);
            split2(s[2*kt+1][2], s[2*kt+1][3], aH[3], aL[3]);
            #pragma unroll
            for (int c = 0; c < 8; c++) {
                const char* vp = smc + (c * 8 + qd) * PITCH + kt * 32 + qq * 4;
                uint32_t bH0 = *(const uint32_t*)(vp + O_VH);
                uint32_t bH1 = *(const uint32_t*)(vp + O_VH + 16);
                uint32_t bL0 = *(const uint32_t*)(vp + O_VL);
                uint32_t bL1 = *(const uint32_t*)(vp + O_VL + 16);
                mma_bf16(o[c], aH, bH0, bH1);
                mma_bf16(o[c], aH, bL0, bL1);
                mma_bf16(o[c], aL, bH0, bH1);
            }
        }
    }

    // ---- epilogue: quad row-sum reduce, normalize, from_mask, store ----
    lsum0 += __shfl_xor_sync(0xffffffffu, lsum0, 1);
    lsum0 += __shfl_xor_sync(0xffffffffu, lsum0, 2);
    lsum1 += __shfl_xor_sync(0xffffffffu, lsum1, 1);
    lsum1 += __shfl_xor_sync(0xffffffffu, lsum1, 2);
    float fm0 = __ldg(from_mask + (size_t)b * SEQL + (size_t)i * 64 + r_lo);
    float fm1 = __ldg(from_mask + (size_t)b * SEQL + (size_t)i * 64 + r_hi);
    float inv0 = fm0 / lsum0;
    float inv1 = fm1 / lsum1;
    float* og = out + ((size_t)bh * SEQL + (size_t)i * 64) * 64;
    #pragma unroll
    for (int c = 0; c < 8; c++) {
        int col = c * 8 + qq * 2;
        float2 w0 = make_float2(o[c][0] * inv0, o[c][1] * inv0);
        float2 w1 = make_float2(o[c][2] * inv1, o[c][3] * inv1);
        *(float2*)(og + (size_t)r_lo * 64 + col) = w0;
        *(float2*)(og + (size_t)r_hi * 64 + col) = w1;
    }
}

extern "C" void kernel_launch(void* const* d_in, const int* in_sizes, int n_in,
                              void* d_out, int out_size)
{
    const float* Q  = (const float*)d_in[0];
    const float* K  = (const float*)d_in[1];
    const float* V  = (const float*)d_in[2];
    const int*   RA = (const int*)  d_in[3];
    const float* FM = (const float*)d_in[4];
    const float* TM = (const float*)d_in[5];
    const float* RM = (const float*)d_in[6];
    const float* BM = (const float*)d_in[7];
    float* O = (float*)d_out;

    cudaFuncSetAttribute(bb_hmma_kernel,
                         cudaFuncAttributeMaxDynamicSharedMemorySize, SMEM_TOTAL);

    dim3 grid(2 * 16 * NB);   // one CTA per (b,h,q-block)
    bb_hmma_kernel<<<grid, 128, SMEM_TOTAL>>>(Q, K, V, RA, FM, TM, RM, BM, O);
}

// round 16
// speedup vs baseline: 2.9944x; 1.6113x over previous
#include <cuda_runtime.h>
#include <cuda_bf16.h>
#include <cstdint>

#define NB    64
#define SEQL  4096
#define NEGM  (-10000.0f)

#define PITCH 144                 // 72 bf16 per row: conflict-free LDSM/STS
#define O_QH  0
#define O_QL  (O_QH + 64*PITCH)   // +9216
#define O_KH  (O_QL + 64*PITCH)
#define O_KL  (O_KH + 64*PITCH)
#define O_VH  (O_KL + 64*PITCH)   // V row-major [key][dim]
#define O_VL  (O_VH + 64*PITCH)
#define SMEM_TOTAL (O_VL + 64*PITCH)   // 55296 B
#define HLSTRIDE (64*PITCH)            // 9216: hi->lo buffer offset

#define TOTKV (2*16*4096*64)           // elements per tensor
__device__ __nv_bfloat16 g_KH[TOTKV], g_KL[TOTKV], g_VH[TOTKV], g_VL[TOTKV];

static __device__ __forceinline__ void mma_bf16(float* d, const uint32_t* a,
                                                uint32_t b0, uint32_t b1) {
    asm volatile("mma.sync.aligned.m16n8k16.row.col.f32.bf16.bf16.f32 "
                 "{%0,%1,%2,%3}, {%4,%5,%6,%7}, {%8,%9}, {%0,%1,%2,%3};"
                 : "+f"(d[0]), "+f"(d[1]), "+f"(d[2]), "+f"(d[3])
                 : "r"(a[0]), "r"(a[1]), "r"(a[2]), "r"(a[3]), "r"(b0), "r"(b1));
}
static __device__ __forceinline__ void ldsm4(uint32_t* r, uint32_t addr) {
    asm volatile("ldmatrix.sync.aligned.m8n8.x4.shared.b16 {%0,%1,%2,%3}, [%4];"
                 : "=r"(r[0]), "=r"(r[1]), "=r"(r[2]), "=r"(r[3]) : "r"(addr));
}
static __device__ __forceinline__ void ldsm4t(uint32_t* r, uint32_t addr) {
    asm volatile("ldmatrix.sync.aligned.m8n8.x4.trans.shared.b16 {%0,%1,%2,%3}, [%4];"
                 : "=r"(r[0]), "=r"(r[1]), "=r"(r[2]), "=r"(r[3]) : "r"(addr));
}
static __device__ __forceinline__ uint32_t s2u(const void* p) {
    uint32_t a;
    asm("{ .reg .u64 t; cvta.to.shared.u64 t, %1; cvt.u32.u64 %0, t; }" : "=r"(a) : "l"(p));
    return a;
}
// split (x,y) into packed bf16 hi word + residual-lo word (low half = x)
static __device__ __forceinline__ void split2(float x, float y, uint32_t& h, uint32_t& l) {
    __nv_bfloat162 bh = __floats2bfloat162_rn(x, y);
    float rx = __bfloat162float(__low2bfloat16(bh));
    float ry = __bfloat162float(__high2bfloat16(bh));
    __nv_bfloat162 bl = __floats2bfloat162_rn(x - rx, y - ry);
    h = *(uint32_t*)&bh; l = *(uint32_t*)&bl;
}

// ---- prepass: K/V fp32 -> bf16 hi/lo global arrays ----
__global__ __launch_bounds__(256)
void kv_conv_kernel(const float* __restrict__ K, const float* __restrict__ V) {
    const size_t N4 = TOTKV / 4;
    size_t idx = (size_t)blockIdx.x * 256 + threadIdx.x;
    const float* src;
    __nv_bfloat16 *dh, *dl;
    size_t j;
    if (idx < N4) { src = K; dh = g_KH; dl = g_KL; j = idx; }
    else          { src = V; dh = g_VH; dl = g_VL; j = idx - N4; }
    float4 t = __ldg((const float4*)src + j);
    uint32_t h0, l0, h1, l1;
    split2(t.x, t.y, h0, l0);
    split2(t.z, t.w, h1, l1);
    *(uint2*)(dh + j * 4) = make_uint2(h0, h1);
    *(uint2*)(dl + j * 4) = make_uint2(l0, l1);
}

__global__ __launch_bounds__(128, 4)
void bb_hmma_kernel(const float*  __restrict__ Q,
                    const int*    __restrict__ rand_attn,
                    const float*  __restrict__ from_mask,
                    const float*  __restrict__ to_mask,
                    const float*  __restrict__ rand_mask,
                    const float*  __restrict__ band_mask,
                    float*        __restrict__ out)
{
    extern __shared__ char smc[];
    const uint32_t smb = s2u(smc);

    // heavy-first remap: full-attention blocks first
    int i, bh;
    {
        int bid = blockIdx.x;
        if (bid < 64) { bh = bid >> 1; i = (bid & 1) ? (NB - 1) : 0; }
        else          { int x = bid - 64; bh = x / 62; i = 1 + (x - bh * 62); }
    }
    const int b    = bh >> 4;
    const int tid  = threadIdx.x;
    const int wid  = tid >> 5;
    const int lane = tid & 31;
    const int qd   = lane >> 2;          // 0..7
    const int qq   = lane & 3;           // 0..3
    const int r_lo = wid * 16 + qd;
    const int r_hi = r_lo + 8;
    const int r8   = lane & 7;

    // LDSM per-thread base addresses
    const uint32_t qaddr = smb + O_QH + (uint32_t)(wid*16 + ((lane>>3)&1)*8 + r8) * PITCH
                         + ((lane>>4) << 4);
    const uint32_t kaddr = smb + O_KH + (uint32_t)(((lane>>4)<<3) + r8) * PITCH
                         + (((lane>>3)&1) << 4);
    const uint32_t vaddr = smb + O_VH + (uint32_t)((((lane>>3)&1)<<3) + r8) * PITCH
                         + ((lane>>4) << 4);

    // ---- load Q -> bf16 hi/lo smem (pre-scaled by 1/8, exact) ----
    {
        const float* Qg = Q + ((size_t)bh * SEQL + (size_t)i * 64) * 64;
        for (int f = tid; f < 1024; f += 128) {
            int row = f >> 4, c4 = (f & 15) << 2;
            float4 t = __ldg((const float4*)(Qg + row * 64 + c4));
            t.x *= 0.125f; t.y *= 0.125f; t.z *= 0.125f; t.w *= 0.125f;
            uint32_t h0, l0, h1, l1;
            split2(t.x, t.y, h0, l0);
            split2(t.z, t.w, h1, l1);
            char* base = smc + row * PITCH + c4 * 2;
            *(uint32_t*)(base + O_QH)     = h0;
            *(uint32_t*)(base + O_QH + 4) = h1;
            *(uint32_t*)(base + O_QL)     = l0;
            *(uint32_t*)(base + O_QL + 4) = l1;
        }
    }

    // ---- key-block list ----
    const bool full = (i == 0 || i == NB - 1);
    int nt;
    int kbl[8], mtl[8], mpl[8];
    if (full) {
        nt = NB;
    } else {
        const int* ra = rand_attn + ((size_t)bh * (NB - 2) + (i - 1)) * 3;
        int r0 = __ldg(ra), r1 = __ldg(ra + 1), r2 = __ldg(ra + 2);
        if (i == 1) {
            kbl[0]=0; kbl[1]=1; kbl[2]=2; kbl[3]=NB-1;
            mtl[0]=mtl[1]=mtl[2]=mtl[3]=0; mpl[0]=mpl[1]=mpl[2]=mpl[3]=0;
            kbl[4]=r0; kbl[5]=r1; kbl[6]=r2;
            mtl[4]=mtl[5]=mtl[6]=2; mpl[4]=0; mpl[5]=1; mpl[6]=2;
            nt = 7;
        } else if (i == NB - 2) {
            kbl[0]=0; kbl[1]=NB-3; kbl[2]=NB-2; kbl[3]=NB-1;
            mtl[0]=mtl[1]=mtl[2]=mtl[3]=0; mpl[0]=mpl[1]=mpl[2]=mpl[3]=0;
            kbl[4]=r0; kbl[5]=r1; kbl[6]=r2;
            mtl[4]=mtl[5]=mtl[6]=2; mpl[4]=0; mpl[5]=1; mpl[6]=2;
            nt = 7;
        } else {
            kbl[0]=0;    mtl[0]=0; mpl[0]=0;
            kbl[1]=i-1;  mtl[1]=1; mpl[1]=0;
            kbl[2]=i;    mtl[2]=1; mpl[2]=1;
            kbl[3]=i+1;  mtl[3]=1; mpl[3]=2;
            kbl[4]=r0;   mtl[4]=2; mpl[4]=0;
            kbl[5]=r1;   mtl[5]=2; mpl[5]=1;
            kbl[6]=r2;   mtl[6]=2; mpl[6]=2;
            kbl[7]=NB-1; mtl[7]=0; mpl[7]=0;
            nt = 8;
        }
    }

    float o[8][4];
    #pragma unroll
    for (int c = 0; c < 8; c++)
        #pragma unroll
        for (int u = 0; u < 4; u++) o[c][u] = 0.0f;
    float lsum0 = 0.0f, lsum1 = 0.0f;

    for (int t = 0; t < nt; t++) {
        int kb, mt, mp;
        if (full) { kb = t; mt = 0; mp = 0; }
        else      { kb = kbl[t]; mt = mtl[t]; mp = mpl[t]; }

        __syncthreads();   // previous tile's MMAs done with K/V smem

        // ---- load pre-converted K/V bf16 hi/lo tiles (no conversion) ----
        {
            const size_t go0 = ((size_t)bh * SEQL + (size_t)kb * 64) * 64;
            const __nv_bfloat16* KHg = g_KH + go0;
            const __nv_bfloat16* KLg = g_KL + go0;
            const __nv_bfloat16* VHg = g_VH + go0;
            const __nv_bfloat16* VLg = g_VL + go0;
            #pragma unroll
            for (int u = 0; u < 4; u++) {
                int f = tid + (u << 7);
                int row = f >> 3;
                int c8  = (f & 7) << 3;                 // bf16 col
                size_t   go = (size_t)row * 64 + c8;
                uint32_t so = (uint32_t)row * PITCH + (uint32_t)c8 * 2;
                *(uint4*)(smc + O_KH + so) = *(const uint4*)(KHg + go);
                *(uint4*)(smc + O_KL + so) = *(const uint4*)(KLg + go);
                *(uint4*)(smc + O_VH + so) = *(const uint4*)(VHg + go);
                *(uint4*)(smc + O_VL + so) = *(const uint4*)(VLg + go);
            }
        }
        __syncthreads();

        // ---- QK^T on HMMA via ldmatrix ----
        float s[8][4];
        #pragma unroll
        for (int c = 0; c < 8; c++)
            #pragma unroll
            for (int u = 0; u < 4; u++) s[c][u] = 0.0f;

        #pragma unroll
        for (int kt = 0; kt < 4; kt++) {
            uint32_t aH[4], aL[4];
            ldsm4(aH, qaddr + kt * 32);
            ldsm4(aL, qaddr + HLSTRIDE + kt * 32);
            #pragma unroll
            for (int cp = 0; cp < 4; cp++) {
                uint32_t bH[4], bL[4];
                ldsm4(bH, kaddr + cp * (16 * PITCH) + kt * 32);
                ldsm4(bL, kaddr + HLSTRIDE + cp * (16 * PITCH) + kt * 32);
                mma_bf16(s[2*cp],   aH, bH[0], bH[1]);
                mma_bf16(s[2*cp],   aH, bL[0], bL[1]);
                mma_bf16(s[2*cp],   aL, bH[0], bH[1]);
                mma_bf16(s[2*cp+1], aH, bH[2], bH[3]);
                mma_bf16(s[2*cp+1], aH, bL[2], bL[3]);
                mma_bf16(s[2*cp+1], aL, bH[2], bH[3]);
            }
        }

        // ---- mask + exp (registers; cols for tile c: 8c+2qq, +1) ----
        if (mt == 0) {
            const float* tmp = to_mask + (size_t)b * SEQL + (size_t)kb * 64;
            #pragma unroll
            for (int c = 0; c < 8; c++) {
                float2 m = __ldg((const float2*)(tmp + c * 8 + qq * 2));
                float t0 = (1.0f - m.x) * NEGM, t1 = (1.0f - m.y) * NEGM;
                s[c][0] += t0; s[c][1] += t1; s[c][2] += t0; s[c][3] += t1;
            }
        } else {
            const float* mbase = (mt == 1)
                ? band_mask + (((size_t)b  * (NB - 4) + (i - 2)) * 64) * 192 + mp * 64
                : rand_mask + (((size_t)bh * (NB - 2) + (i - 1)) * 64) * 192 + mp * 64;
            const float* mlo = mbase + (size_t)r_lo * 192;
            const float* mhi = mbase + (size_t)r_hi * 192;
            #pragma unroll
            for (int c = 0; c < 8; c++) {
                float2 m0 = __ldg((const float2*)(mlo + c * 8 + qq * 2));
                float2 m1 = __ldg((const float2*)(mhi + c * 8 + qq * 2));
                s[c][0] += (1.0f - m0.x) * NEGM; s[c][1] += (1.0f - m0.y) * NEGM;
                s[c][2] += (1.0f - m1.x) * NEGM; s[c][3] += (1.0f - m1.y) * NEGM;
            }
        }
        #pragma unroll
        for (int c = 0; c < 8; c++) {
            s[c][0] = __expf(s[c][0]); s[c][1] = __expf(s[c][1]);
            s[c][2] = __expf(s[c][2]); s[c][3] = __expf(s[c][3]);
            lsum0 += s[c][0] + s[c][1];
            lsum1 += s[c][2] + s[c][3];
        }

        // ---- PV on HMMA: P A-frags repacked from S regs, V via ldmatrix.trans ----
        #pragma unroll
        for (int kt = 0; kt < 4; kt++) {
            uint32_t aH[4], aL[4];
            split2(s[2*kt][0],   s[2*kt][1],   aH[0], aL[0]);
            split2(s[2*kt][2],   s[2*kt][3],   aH[1], aL[1]);
            split2(s[2*kt+1][0], s[2*kt+1][1], aH[2], aL[2]);
            split2(s[2*kt+1][2], s[2*kt+1][3], aH[3], aL[3]);
            #pragma unroll
            for (int cp = 0; cp < 4; cp++) {
                uint32_t bH[4], bL[4];
                ldsm4t(bH, vaddr + kt * (16 * PITCH) + cp * 32);
                ldsm4t(bL, vaddr + HLSTRIDE + kt * (16 * PITCH) + cp * 32);
                mma_bf16(o[2*cp],   aH, bH[0], bH[1]);
                mma_bf16(o[2*cp],   aH, bL[0], bL[1]);
                mma_bf16(o[2*cp],   aL, bH[0], bH[1]);
                mma_bf16(o[2*cp+1], aH, bH[2], bH[3]);
                mma_bf16(o[2*cp+1], aH, bL[2], bL[3]);
                mma_bf16(o[2*cp+1], aL, bH[2], bH[3]);
            }
        }
    }

    // ---- epilogue: quad row-sum reduce, normalize, from_mask, store ----
    lsum0 += __shfl_xor_sync(0xffffffffu, lsum0, 1);
    lsum0 += __shfl_xor_sync(0xffffffffu, lsum0, 2);
    lsum1 += __shfl_xor_sync(0xffffffffu, lsum1, 1);
    lsum1 += __shfl_xor_sync(0xffffffffu, lsum1, 2);
    float fm0 = __ldg(from_mask + (size_t)b * SEQL + (size_t)i * 64 + r_lo);
    float fm1 = __ldg(from_mask + (size_t)b * SEQL + (size_t)i * 64 + r_hi);
    float inv0 = fm0 / lsum0;
    float inv1 = fm1 / lsum1;
    float* og = out + ((size_t)bh * SEQL + (size_t)i * 64) * 64;
    #pragma unroll
    for (int c = 0; c < 8; c++) {
        int col = c * 8 + qq * 2;
        *(float2*)(og + (size_t)r_lo * 64 + col) = make_float2(o[c][0] * inv0, o[c][1] * inv0);
        *(float2*)(og + (size_t)r_hi * 64 + col) = make_float2(o[c][2] * inv1, o[c][3] * inv1);
    }
}

extern "C" void kernel_launch(void* const* d_in, const int* in_sizes, int n_in,
                              void* d_out, int out_size)
{
    const float* Q  = (const float*)d_in[0];
    const float* K  = (const float*)d_in[1];
    const float* V  = (const float*)d_in[2];
    const int*   RA = (const int*)  d_in[3];
    const float* FM = (const float*)d_in[4];
    const float* TM = (const float*)d_in[5];
    const float* RM = (const float*)d_in[6];
    const float* BM = (const float*)d_in[7];
    float* O = (float*)d_out;

    // prepass: convert K/V to bf16 hi/lo scratch (2*TOTKV/4 float4's, 256 thr)
    kv_conv_kernel<<<(2 * (TOTKV / 4) + 255) / 256, 256>>>(K, V);

    cudaFuncSetAttribute(bb_hmma_kernel,
                         cudaFuncAttributeMaxDynamicSharedMemorySize, SMEM_TOTAL);
    bb_hmma_kernel<<<2 * 16 * NB, 128, SMEM_TOTAL>>>(Q, RA, FM, TM, RM, BM, O);
}

// round 17
// speedup vs baseline: 3.0059x; 1.0038x over previous
#include <cuda_runtime.h>
#include <cuda_bf16.h>
#include <cstdint>

#define NB    64
#define SEQL  4096
#define NEGM  (-10000.0f)

#define PITCH 144                 // 72 bf16 per row: conflict-free LDSM/STS/cp.async
#define O_QH  0
#define O_QL  9216
#define STG0  18432               // stage base; per stage: KH+0, KL+9216, VH+18432, VL+27648
#define STGSZ 36864
#define SMEM_TOTAL (STG0 + 2*STGSZ)    // 92160 B
#define HLSTRIDE 9216                  // hi -> lo offset (all arrays)

#define TOTKV (2*16*4096*64)           // elements per tensor
__device__ __nv_bfloat16 g_KH[TOTKV], g_KL[TOTKV], g_VH[TOTKV], g_VL[TOTKV];

static __device__ __forceinline__ void mma_bf16(float* d, const uint32_t* a,
                                                uint32_t b0, uint32_t b1) {
    asm volatile("mma.sync.aligned.m16n8k16.row.col.f32.bf16.bf16.f32 "
                 "{%0,%1,%2,%3}, {%4,%5,%6,%7}, {%8,%9}, {%0,%1,%2,%3};"
                 : "+f"(d[0]), "+f"(d[1]), "+f"(d[2]), "+f"(d[3])
                 : "r"(a[0]), "r"(a[1]), "r"(a[2]), "r"(a[3]), "r"(b0), "r"(b1));
}
static __device__ __forceinline__ void ldsm4(uint32_t* r, uint32_t addr) {
    asm volatile("ldmatrix.sync.aligned.m8n8.x4.shared.b16 {%0,%1,%2,%3}, [%4];"
                 : "=r"(r[0]), "=r"(r[1]), "=r"(r[2]), "=r"(r[3]) : "r"(addr));
}
static __device__ __forceinline__ void ldsm4t(uint32_t* r, uint32_t addr) {
    asm volatile("ldmatrix.sync.aligned.m8n8.x4.trans.shared.b16 {%0,%1,%2,%3}, [%4];"
                 : "=r"(r[0]), "=r"(r[1]), "=r"(r[2]), "=r"(r[3]) : "r"(addr));
}
static __device__ __forceinline__ uint32_t s2u(const void* p) {
    uint32_t a;
    asm("{ .reg .u64 t; cvta.to.shared.u64 t, %1; cvt.u32.u64 %0, t; }" : "=r"(a) : "l"(p));
    return a;
}
static __device__ __forceinline__ void cpa16(uint32_t saddr, const void* gaddr) {
    asm volatile("cp.async.cg.shared.global [%0], [%1], 16;" :: "r"(saddr), "l"(gaddr) : "memory");
}
// split (x,y) into packed bf16 hi word + residual-lo word (low half = x)
static __device__ __forceinline__ void split2(float x, float y, uint32_t& h, uint32_t& l) {
    __nv_bfloat162 bh = __floats2bfloat162_rn(x, y);
    float rx = __bfloat162float(__low2bfloat16(bh));
    float ry = __bfloat162float(__high2bfloat16(bh));
    __nv_bfloat162 bl = __floats2bfloat162_rn(x - rx, y - ry);
    h = *(uint32_t*)&bh; l = *(uint32_t*)&bl;
}

// ---- prepass: K/V fp32 -> bf16 hi/lo global arrays ----
__global__ __launch_bounds__(256)
void kv_conv_kernel(const float* __restrict__ K, const float* __restrict__ V) {
    const size_t N4 = TOTKV / 4;
    size_t idx = (size_t)blockIdx.x * 256 + threadIdx.x;
    const float* src;
    __nv_bfloat16 *dh, *dl;
    size_t j;
    if (idx < N4) { src = K; dh = g_KH; dl = g_KL; j = idx; }
    else          { src = V; dh = g_VH; dl = g_VL; j = idx - N4; }
    float4 t = __ldg((const float4*)src + j);
    uint32_t h0, l0, h1, l1;
    split2(t.x, t.y, h0, l0);
    split2(t.z, t.w, h1, l1);
    *(uint2*)(dh + j * 4) = make_uint2(h0, h1);
    *(uint2*)(dl + j * 4) = make_uint2(l0, l1);
}

__global__ __launch_bounds__(128, 2)
void bb_hmma_kernel(const float*  __restrict__ Q,
                    const int*    __restrict__ rand_attn,
                    const float*  __restrict__ from_mask,
                    const float*  __restrict__ to_mask,
                    const float*  __restrict__ rand_mask,
                    const float*  __restrict__ band_mask,
                    float*        __restrict__ out)
{
    extern __shared__ char smc[];
    const uint32_t smb = s2u(smc);

    // heavy-first remap: full-attention blocks first
    int i, bh;
    {
        int bid = blockIdx.x;
        if (bid < 64) { bh = bid >> 1; i = (bid & 1) ? (NB - 1) : 0; }
        else          { int x = bid - 64; bh = x / 62; i = 1 + (x - bh * 62); }
    }
    const int b    = bh >> 4;
    const int tid  = threadIdx.x;
    const int wid  = tid >> 5;
    const int lane = tid & 31;
    const int qq   = lane & 3;
    const int r_lo = wid * 16 + (lane >> 2);
    const int r_hi = r_lo + 8;
    const int r8   = lane & 7;

    // LDSM per-thread addresses (k/v relative to stage's KH/VH base)
    const uint32_t qaddr = smb + O_QH + (uint32_t)(wid*16 + ((lane>>3)&1)*8 + r8) * PITCH
                         + ((lane>>4) << 4);
    const uint32_t krel  = (uint32_t)(((lane>>4)<<3) + r8) * PITCH + (((lane>>3)&1) << 4);
    const uint32_t vrel  = (uint32_t)((((lane>>3)&1)<<3) + r8) * PITCH + ((lane>>4) << 4);

    // ---- key-block list ----
    const bool full = (i == 0 || i == NB - 1);
    int nt;
    int kbl[8], mtl[8], mpl[8];
    if (full) {
        nt = NB;
    } else {
        const int* ra = rand_attn + ((size_t)bh * (NB - 2) + (i - 1)) * 3;
        int r0 = __ldg(ra), r1 = __ldg(ra + 1), r2 = __ldg(ra + 2);
        if (i == 1) {
            kbl[0]=0; kbl[1]=1; kbl[2]=2; kbl[3]=NB-1;
            mtl[0]=mtl[1]=mtl[2]=mtl[3]=0; mpl[0]=mpl[1]=mpl[2]=mpl[3]=0;
            kbl[4]=r0; kbl[5]=r1; kbl[6]=r2;
            mtl[4]=mtl[5]=mtl[6]=2; mpl[4]=0; mpl[5]=1; mpl[6]=2;
            nt = 7;
        } else if (i == NB - 2) {
            kbl[0]=0; kbl[1]=NB-3; kbl[2]=NB-2; kbl[3]=NB-1;
            mtl[0]=mtl[1]=mtl[2]=mtl[3]=0; mpl[0]=mpl[1]=mpl[2]=mpl[3]=0;
            kbl[4]=r0; kbl[5]=r1; kbl[6]=r2;
            mtl[4]=mtl[5]=mtl[6]=2; mpl[4]=0; mpl[5]=1; mpl[6]=2;
            nt = 7;
        } else {
            kbl[0]=0;    mtl[0]=0; mpl[0]=0;
            kbl[1]=i-1;  mtl[1]=1; mpl[1]=0;
            kbl[2]=i;    mtl[2]=1; mpl[2]=1;
            kbl[3]=i+1;  mtl[3]=1; mpl[3]=2;
            kbl[4]=r0;   mtl[4]=2; mpl[4]=0;
            kbl[5]=r1;   mtl[5]=2; mpl[5]=1;
            kbl[6]=r2;   mtl[6]=2; mpl[6]=2;
            kbl[7]=NB-1; mtl[7]=0; mpl[7]=0;
            nt = 8;
        }
    }

    // issue cp.async group for one tile into a stage
    auto issue_tile = [&](int kb, int stg) {
        const size_t go0 = ((size_t)bh * SEQL + (size_t)kb * 64) * 64;
        const uint32_t sb = smb + STG0 + (uint32_t)stg * STGSZ;
        #pragma unroll
        for (int u = 0; u < 4; u++) {
            int f = tid + (u << 7);
            uint32_t so = (uint32_t)(f >> 3) * PITCH + (uint32_t)(f & 7) * 16;
            size_t   go = go0 + (size_t)(f >> 3) * 64 + (size_t)(f & 7) * 8;
            cpa16(sb + so,         g_KH + go);
            cpa16(sb + 9216  + so, g_KL + go);
            cpa16(sb + 18432 + so, g_VH + go);
            cpa16(sb + 27648 + so, g_VL + go);
        }
        asm volatile("cp.async.commit_group;" ::: "memory");
    };

    // prologue: start tile 0, then convert Q while it flies
    {
        int kb0 = full ? 0 : kbl[0];
        issue_tile(kb0, 0);
    }
    {
        const float* Qg = Q + ((size_t)bh * SEQL + (size_t)i * 64) * 64;
        for (int f = tid; f < 1024; f += 128) {
            int row = f >> 4, c4 = (f & 15) << 2;
            float4 t = __ldg((const float4*)(Qg + row * 64 + c4));
            t.x *= 0.125f; t.y *= 0.125f; t.z *= 0.125f; t.w *= 0.125f;
            uint32_t h0, l0, h1, l1;
            split2(t.x, t.y, h0, l0);
            split2(t.z, t.w, h1, l1);
            char* base = smc + row * PITCH + c4 * 2;
            *(uint32_t*)(base + O_QH)     = h0;
            *(uint32_t*)(base + O_QH + 4) = h1;
            *(uint32_t*)(base + O_QL)     = l0;
            *(uint32_t*)(base + O_QL + 4) = l1;
        }
    }

    float o[8][4];
    #pragma unroll
    for (int c = 0; c < 8; c++)
        #pragma unroll
        for (int u = 0; u < 4; u++) o[c][u] = 0.0f;
    float lsum0 = 0.0f, lsum1 = 0.0f;

    for (int t = 0; t < nt; t++) {
        int kb, mt, mp;
        if (full) { kb = t; mt = 0; mp = 0; }
        else      { kb = kbl[t]; mt = mtl[t]; mp = mpl[t]; }
        const int stg = t & 1;

        asm volatile("cp.async.wait_group 0;" ::: "memory");
        __syncthreads();   // tile t resident; all warps done with stage !stg (tile t-1)

        if (t + 1 < nt)    // prefetch next tile into the other stage
            issue_tile(full ? (t + 1) : kbl[t + 1], stg ^ 1);

        const uint32_t kbase = smb + STG0 + (uint32_t)stg * STGSZ;
        const uint32_t kaddr = kbase + krel;
        const uint32_t vaddr = kbase + 18432 + vrel;

        // ---- QK^T on HMMA via ldmatrix ----
        float s[8][4];
        #pragma unroll
        for (int c = 0; c < 8; c++)
            #pragma unroll
            for (int u = 0; u < 4; u++) s[c][u] = 0.0f;

        #pragma unroll
        for (int kt = 0; kt < 4; kt++) {
            uint32_t aH[4], aL[4];
            ldsm4(aH, qaddr + kt * 32);
            ldsm4(aL, qaddr + HLSTRIDE + kt * 32);
            #pragma unroll
            for (int cp = 0; cp < 4; cp++) {
                uint32_t bH[4], bL[4];
                ldsm4(bH, kaddr + cp * (16 * PITCH) + kt * 32);
                ldsm4(bL, kaddr + HLSTRIDE + cp * (16 * PITCH) + kt * 32);
                mma_bf16(s[2*cp],   aH, bH[0], bH[1]);
                mma_bf16(s[2*cp],   aH, bL[0], bL[1]);
                mma_bf16(s[2*cp],   aL, bH[0], bH[1]);
                mma_bf16(s[2*cp+1], aH, bH[2], bH[3]);
                mma_bf16(s[2*cp+1], aH, bL[2], bL[3]);
                mma_bf16(s[2*cp+1], aL, bH[2], bH[3]);
            }
        }

        // ---- mask + exp (registers; cols for tile c: 8c+2qq, +1) ----
        if (mt == 0) {
            const float* tmp = to_mask + (size_t)b * SEQL + (size_t)kb * 64;
            #pragma unroll
            for (int c = 0; c < 8; c++) {
                float2 m = __ldg((const float2*)(tmp + c * 8 + qq * 2));
                float t0 = (1.0f - m.x) * NEGM, t1 = (1.0f - m.y) * NEGM;
                s[c][0] += t0; s[c][1] += t1; s[c][2] += t0; s[c][3] += t1;
            }
        } else {
            const float* mbase = (mt == 1)
                ? band_mask + (((size_t)b  * (NB - 4) + (i - 2)) * 64) * 192 + mp * 64
                : rand_mask + (((size_t)bh * (NB - 2) + (i - 1)) * 64) * 192 + mp * 64;
            const float* mlo = mbase + (size_t)r_lo * 192;
            const float* mhi = mbase + (size_t)r_hi * 192;
            #pragma unroll
            for (int c = 0; c < 8; c++) {
                float2 m0 = __ldg((const float2*)(mlo + c * 8 + qq * 2));
                float2 m1 = __ldg((const float2*)(mhi + c * 8 + qq * 2));
                s[c][0] += (1.0f - m0.x) * NEGM; s[c][1] += (1.0f - m0.y) * NEGM;
                s[c][2] += (1.0f - m1.x) * NEGM; s[c][3] += (1.0f - m1.y) * NEGM;
            }
        }
        #pragma unroll
        for (int c = 0; c < 8; c++) {
            s[c][0] = __expf(s[c][0]); s[c][1] = __expf(s[c][1]);
            s[c][2] = __expf(s[c][2]); s[c][3] = __expf(s[c][3]);
            lsum0 += s[c][0] + s[c][1];
            lsum1 += s[c][2] + s[c][3];
        }

        // ---- PV on HMMA: P A-frags repacked from S regs, V via ldmatrix.trans ----
        #pragma unroll
        for (int kt = 0; kt < 4; kt++) {
            uint32_t aH[4], aL[4];
            split2(s[2*kt][0],   s[2*kt][1],   aH[0], aL[0]);
            split2(s[2*kt][2],   s[2*kt][3],   aH[1], aL[1]);
            split2(s[2*kt+1][0], s[2*kt+1][1], aH[2], aL[2]);
            split2(s[2*kt+1][2], s[2*kt+1][3], aH[3], aL[3]);
            #pragma unroll
            for (int cp = 0; cp < 4; cp++) {
                uint32_t bH[4], bL[4];
                ldsm4t(bH, vaddr + kt * (16 * PITCH) + cp * 32);
                ldsm4t(bL, vaddr + HLSTRIDE + kt * (16 * PITCH) + cp * 32);
                mma_bf16(o[2*cp],   aH, bH[0], bH[1]);
                mma_bf16(o[2*cp],   aH, bL[0], bL[1]);
                mma_bf16(o[2*cp],   aL, bH[0], bH[1]);
                mma_bf16(o[2*cp+1], aH, bH[2], bH[3]);
                mma_bf16(o[2*cp+1], aH, bL[2], bL[3]);
                mma_bf16(o[2*cp+1], aL, bH[2], bH[3]);
            }
        }
    }

    // ---- epilogue: quad row-sum reduce, normalize, from_mask, store ----
    lsum0 += __shfl_xor_sync(0xffffffffu, lsum0, 1);
    lsum0 += __shfl_xor_sync(0xffffffffu, lsum0, 2);
    lsum1 += __shfl_xor_sync(0xffffffffu, lsum1, 1);
    lsum1 += __shfl_xor_sync(0xffffffffu, lsum1, 2);
    float fm0 = __ldg(from_mask + (size_t)b * SEQL + (size_t)i * 64 + r_lo);
    float fm1 = __ldg(from_mask + (size_t)b * SEQL + (size_t)i * 64 + r_hi);
    float inv0 = fm0 / lsum0;
    float inv1 = fm1 / lsum1;
    float* og = out + ((size_t)bh * SEQL + (size_t)i * 64) * 64;
    #pragma unroll
    for (int c = 0; c < 8; c++) {
        int col = c * 8 + qq * 2;
        *(float2*)(og + (size_t)r_lo * 64 + col) = make_float2(o[c][0] * inv0, o[c][1] * inv0);
        *(float2*)(og + (size_t)r_hi * 64 + col) = make_float2(o[c][2] * inv1, o[c][3] * inv1);
    }
}

extern "C" void kernel_launch(void* const* d_in, const int* in_sizes, int n_in,
                              void* d_out, int out_size)
{
    const float* Q  = (const float*)d_in[0];
    const float* K  = (const float*)d_in[1];
    const float* V  = (const float*)d_in[2];
    const int*   RA = (const int*)  d_in[3];
    const float* FM = (const float*)d_in[4];
    const float* TM = (const float*)d_in[5];
    const float* RM = (const float*)d_in[6];
    const float* BM = (const float*)d_in[7];
    float* O = (float*)d_out;

    kv_conv_kernel<<<(2 * (TOTKV / 4) + 255) / 256, 256>>>(K, V);

    cudaFuncSetAttribute(bb_hmma_kernel,
                         cudaFuncAttributeMaxDynamicSharedMemorySize, SMEM_TOTAL);
    bb_hmma_kernel<<<2 * 16 * NB, 128, SMEM_TOTAL>>>(Q, RA, FM, TM, RM, BM, O);
}